// round 10
// baseline (speedup 1.0000x reference)
#include <cuda_runtime.h>
#include <cuda_bf16.h>
#include <mma.h>
#include <math.h>
#include <stdint.h>

using namespace nvcuda;

#define N_NODES 50000
#define N_EDGES 800000
#define IN_DIM  128
#define FEAT    64
#define SCAN_BLOCKS 196   // ceil(50001/256)

typedef unsigned long long u64;

// ---------------- scratch (static device globals; no allocation) ----------------
__device__ float    g_H0[N_NODES * FEAT];
__device__ float    g_H1[N_NODES * FEAT];
__device__ unsigned g_Ahi[N_NODES * 96];     // split-bf16 A, packed bf16x2, row stride K/2 words
__device__ unsigned g_Alo[N_NODES * 96];
__device__ __nv_bfloat16 g_Bhi[192 * 64];    // split-bf16 B, row-major [K,64]
__device__ __nv_bfloat16 g_Blo[192 * 64];
__device__ int      g_cnt[N_NODES];
__device__ int      g_off[N_NODES + 1];
__device__ int      g_pos[N_NODES];
__device__ int      g_csr[N_EDGES];
__device__ int      g_bsum[256];

__device__ __forceinline__ float* sel_buf(int s) { return (s == 0) ? g_H0 : g_H1; }

__device__ __forceinline__ unsigned pack_bf2(__nv_bfloat16 a, __nv_bfloat16 b) {
    return ((unsigned)__bfloat16_as_ushort(b) << 16) | (unsigned)__bfloat16_as_ushort(a);
}
__device__ __forceinline__ void split2(float x, float y, unsigned& hi, unsigned& lo) {
    __nv_bfloat16 hx = __float2bfloat16(x), hy = __float2bfloat16(y);
    __nv_bfloat16 lx = __float2bfloat16(x - __bfloat162float(hx));
    __nv_bfloat16 ly = __float2bfloat16(y - __bfloat162float(hy));
    hi = pack_bf2(hx, hy);
    lo = pack_bf2(lx, ly);
}

// ---------------- CSR build ----------------
__global__ void zero_cnt_kernel() {
    int i = blockIdx.x * blockDim.x + threadIdx.x;
    if (i < N_NODES) g_cnt[i] = 0;
}
__global__ void count_kernel(const int* __restrict__ ei) {
    int e = blockIdx.x * blockDim.x + threadIdx.x;
    if (e < N_EDGES) atomicAdd(&g_cnt[ei[N_EDGES + e]], 1);
}
__global__ void scan1_kernel() {
    __shared__ int s[256];
    int t = threadIdx.x, i = blockIdx.x * 256 + t;
    int v = (i < N_NODES) ? g_cnt[i] : 0;
    s[t] = v; __syncthreads();
    #pragma unroll
    for (int d = 1; d < 256; d <<= 1) {
        int x = (t >= d) ? s[t - d] : 0;
        __syncthreads(); s[t] += x; __syncthreads();
    }
    if (i < N_NODES) g_off[i] = s[t] - v;
    if (t == 255) g_bsum[blockIdx.x] = s[255];
}
__global__ void scan23_kernel() {
    __shared__ int s[256];
    int t = threadIdx.x;
    s[t] = (t < SCAN_BLOCKS) ? g_bsum[t] : 0;
    __syncthreads();
    #pragma unroll
    for (int d = 1; d < 256; d <<= 1) {
        int x = (t >= d) ? s[t - d] : 0;
        __syncthreads(); s[t] += x; __syncthreads();
    }
    int blk = blockIdx.x;
    int add = (blk == 0) ? 0 : s[blk - 1];
    int i = blk * 256 + t;
    if (i < N_NODES) { int o = g_off[i] + add; g_off[i] = o; g_pos[i] = o; }
    if (i == N_NODES) g_off[N_NODES] = N_EDGES;
}
__global__ void fill_csr_kernel(const int* __restrict__ ei) {
    int e = blockIdx.x * blockDim.x + threadIdx.x;
    if (e < N_EDGES) {
        int t = ei[N_EDGES + e];
        g_csr[atomicAdd(&g_pos[t], 1)] = e;
    }
}

// ---------------- x -> split-bf16 A (K=128, row stride 64 words) ----------------
__global__ void convert_x_kernel(const float* __restrict__ x) {
    int idx = blockIdx.x * blockDim.x + threadIdx.x;
    if (idx >= N_NODES * 64) return;
    float2 v = ((const float2*)x)[idx];
    unsigned hi, lo;
    split2(v.x, v.y, hi, lo);
    g_Ahi[idx] = hi;
    g_Alo[idx] = lo;
}

// ---------------- W[K,64] -> split-bf16 B row-major ----------------
__global__ void prep_b_kernel(const float* __restrict__ W, int K) {
    int idx = blockIdx.x * blockDim.x + threadIdx.x;   // k*64 + n
    if (idx >= K * 64) return;
    float wv = W[idx];
    __nv_bfloat16 hi = __float2bfloat16(wv);
    g_Bhi[idx] = hi;
    g_Blo[idx] = __float2bfloat16(wv - __bfloat162float(hi));
}

// ---------------- edge aggregation -> split-bf16 A rows (K=192, stride 96 words) ----
__global__ void agg_kernel(const int* __restrict__ ei,
                           const float* __restrict__ ea, int hsel)
{
    __shared__ float4 sE[8][32];
    int w = threadIdx.x >> 5;
    int node = blockIdx.x * 8 + w;
    if (node >= N_NODES) return;
    int lane = threadIdx.x & 31;
    const float* H = sel_buf(hsel);
    int off = g_off[node];
    int deg = g_off[node + 1] - off;

    float s0x = 0.f, s0y = 0.f, s1x = 0.f, s1y = 0.f, s2x = 0.f, s2y = 0.f;

    for (int base = 0; base < deg; base += 32) {
        if (base + lane < deg) {
            int eid = __ldg(&g_csr[off + base + lane]);
            int src = __ldg(&ei[eid]);
            float a0 = __ldg(&ea[(size_t)eid * 3 + 0]);
            float a1 = __ldg(&ea[(size_t)eid * 3 + 1]);
            float a2 = __ldg(&ea[(size_t)eid * 3 + 2]);
            sE[w][lane] = make_float4(__int_as_float(src), a0, a1, a2);
        }
        __syncwarp();
        int m = min(32, deg - base);
        for (int k = 0; k < m; k++) {
            float4 ed = sE[w][k];
            int src = __float_as_int(ed.x);
            float2 hv = __ldg(&((const float2*)(H + (size_t)src * 64))[lane]);
            s0x += ed.y * hv.x; s0y += ed.y * hv.y;
            s1x += ed.z * hv.x; s1y += ed.z * hv.y;
            s2x += ed.w * hv.x; s2y += ed.w * hv.y;
        }
        __syncwarp();
    }

    float inv = 1.0f / fmaxf((float)deg, 1.0f);
    size_t rb = (size_t)node * 96;
    unsigned hi, lo;
    split2(s0x * inv, s0y * inv, hi, lo); g_Ahi[rb + lane]      = hi; g_Alo[rb + lane]      = lo;
    split2(s1x * inv, s1y * inv, hi, lo); g_Ahi[rb + 32 + lane] = hi; g_Alo[rb + 32 + lane] = lo;
    split2(s2x * inv, s2y * inv, hi, lo); g_Ahi[rb + 64 + lane] = hi; g_Alo[rb + 64 + lane] = lo;
}

// ---------------- WMMA bf16 split GEMM, fused epilogue ----------------
// D[row,n] = sum_k A[row,k]*W[k,n] (+bias; opt relu / row L2-norm).
// 256 threads = 8 warps; warp tile 16 rows x 64 cols (4 m16n16k16 frags).
// Split: D = Ahi*Bhi + Alo*Bhi + Ahi*Blo (AloBlo term ~2^-16 rel, dropped).
__global__ void __launch_bounds__(256)
gemm_wmma(int K, const float* __restrict__ bias,
          int do_relu, int do_norm, int csel, float* __restrict__ extout)
{
    __shared__ float sOut[8][16 * 64];   // 32 KB: per-warp epilogue tile

    const int wid = threadIdx.x >> 5;
    const int lane = threadIdx.x & 31;
    const int row0 = blockIdx.x * 128 + wid * 16;
    if (row0 >= N_NODES) return;       // 50000 % 16 == 0: tiles fully in or out

    const __nv_bfloat16* Ah = (const __nv_bfloat16*)g_Ahi + (size_t)row0 * K;
    const __nv_bfloat16* Al = (const __nv_bfloat16*)g_Alo + (size_t)row0 * K;

    wmma::fragment<wmma::accumulator, 16, 16, 16, float> acc[4];
    #pragma unroll
    for (int j = 0; j < 4; j++) wmma::fill_fragment(acc[j], 0.0f);

    for (int k0 = 0; k0 < K; k0 += 16) {
        wmma::fragment<wmma::matrix_a, 16, 16, 16, __nv_bfloat16, wmma::row_major> ah, al;
        wmma::load_matrix_sync(ah, Ah + k0, K);
        wmma::load_matrix_sync(al, Al + k0, K);
        #pragma unroll
        for (int j = 0; j < 4; j++) {
            wmma::fragment<wmma::matrix_b, 16, 16, 16, __nv_bfloat16, wmma::row_major> bh, bl;
            wmma::load_matrix_sync(bh, g_Bhi + (size_t)k0 * 64 + j * 16, 64);
            wmma::load_matrix_sync(bl, g_Blo + (size_t)k0 * 64 + j * 16, 64);
            wmma::mma_sync(acc[j], ah, bh, acc[j]);
            wmma::mma_sync(acc[j], al, bh, acc[j]);
            wmma::mma_sync(acc[j], ah, bl, acc[j]);
        }
    }

    #pragma unroll
    for (int j = 0; j < 4; j++)
        wmma::store_matrix_sync(&sOut[wid][j * 16], acc[j], 64, wmma::mem_row_major);
    __syncwarp();

    // epilogue: 2 lanes per row (lane = r + 16*half); half covers 32 cols
    int r = lane & 15, half = lane >> 4;
    const float* src = &sOut[wid][r * 64 + half * 32];
    float v[32];
    float ss = 0.0f;
    #pragma unroll
    for (int j = 0; j < 32; j++) {
        v[j] = src[j] + __ldg(&bias[half * 32 + j]);
        if (do_relu) v[j] = fmaxf(v[j], 0.0f);
        ss += v[j] * v[j];
    }
    if (do_norm) {
        ss += __shfl_xor_sync(0xffffffffu, ss, 16);  // combine halves of same row
        float rr = 1.0f / fmaxf(sqrtf(ss), 1e-12f);
        #pragma unroll
        for (int j = 0; j < 32; j++) v[j] *= rr;
    }
    float* C = (csel < 0) ? extout : sel_buf(csel);
    float4* po = (float4*)(C + (size_t)(row0 + r) * 64 + half * 32);
    #pragma unroll
    for (int j = 0; j < 8; j++)
        po[j] = make_float4(v[4 * j], v[4 * j + 1], v[4 * j + 2], v[4 * j + 3]);
}

// ---------------- launch (kernel launches ONLY — graph-capture safe) ----------------
extern "C" void kernel_launch(void* const* d_in, const int* in_sizes, int n_in,
                              void* d_out, int out_size)
{
    const float* x     = (const float*)d_in[0];
    const int*   ei    = (const int*)  d_in[1];   // [2, E]
    const float* ea    = (const float*)d_in[2];   // [E, 3]
    const float* pre_w = (const float*)d_in[3];   // [128, 64]
    const float* pre_b = (const float*)d_in[4];   // [64]
    const float* w[3]  = {(const float*)d_in[5], (const float*)d_in[7], (const float*)d_in[9]};
    const float* b[3]  = {(const float*)d_in[6], (const float*)d_in[8], (const float*)d_in[10]};
    float* out = (float*)d_out;

    const int gemm_blocks = (N_NODES + 127) / 128;   // 391

    // ---- CSR build ----
    zero_cnt_kernel<<<(N_NODES + 255) / 256, 256>>>();
    count_kernel<<<(N_EDGES + 255) / 256, 256>>>(ei);
    scan1_kernel<<<SCAN_BLOCKS, 256>>>();
    scan23_kernel<<<SCAN_BLOCKS + 1, 256>>>();
    fill_csr_kernel<<<(N_EDGES + 255) / 256, 256>>>(ei);

    // ---- linear_pre: H0 = x @ pre_w + pre_b (WMMA, K=128) ----
    convert_x_kernel<<<(N_NODES * 64 + 255) / 256, 256>>>(x);
    prep_b_kernel<<<(IN_DIM * 64 + 255) / 256, 256>>>(pre_w, IN_DIM);
    gemm_wmma<<<gemm_blocks, 256>>>(IN_DIM, pre_b, 0, 0, 0, nullptr);

    int hin = 0, hout = 1;
    for (int l = 0; l < 3; l++) {
        agg_kernel<<<(N_NODES + 7) / 8, 256>>>(ei, ea, hin);       // -> split-bf16 A (K=192)
        prep_b_kernel<<<(192 * 64 + 255) / 256, 256>>>(w[l], 192);
        if (l < 2) {
            gemm_wmma<<<gemm_blocks, 256>>>(192, b[l], 1, 0, hout, nullptr);
        } else {
            gemm_wmma<<<gemm_blocks, 256>>>(192, b[l], 0, 1, -1, out);
        }
        int t = hin; hin = hout; hout = t;
    }
}

// round 11
// speedup vs baseline: 1.3404x; 1.3404x over previous
#include <cuda_runtime.h>
#include <cuda_bf16.h>
#include <mma.h>
#include <math.h>
#include <stdint.h>

using namespace nvcuda;

#define N_NODES 50000
#define N_EDGES 800000
#define IN_DIM  128
#define FEAT    64
#define SCAN_BLOCKS 196   // ceil(50001/256)

// ---------------- scratch (static device globals; no allocation) ----------------
__device__ float    g_H0[N_NODES * FEAT];
__device__ float    g_H1[N_NODES * FEAT];
__device__ unsigned g_Ahi[N_NODES * 96];     // split-bf16 A, packed bf16x2, row stride K/2 words
__device__ unsigned g_Alo[N_NODES * 96];
__device__ __nv_bfloat16 g_Bhi[192 * 64];    // split-bf16 B, row-major [K,64]
__device__ __nv_bfloat16 g_Blo[192 * 64];
__device__ int      g_cnt[N_NODES];
__device__ int      g_off[N_NODES + 1];
__device__ int      g_pos[N_NODES];
__device__ int      g_csr[N_EDGES];
__device__ int      g_bsum[256];

__device__ __forceinline__ float* sel_buf(int s) { return (s == 0) ? g_H0 : g_H1; }

__device__ __forceinline__ unsigned pack_bf2(__nv_bfloat16 a, __nv_bfloat16 b) {
    return ((unsigned)__bfloat16_as_ushort(b) << 16) | (unsigned)__bfloat16_as_ushort(a);
}
__device__ __forceinline__ void split2(float x, float y, unsigned& hi, unsigned& lo) {
    __nv_bfloat16 hx = __float2bfloat16(x), hy = __float2bfloat16(y);
    __nv_bfloat16 lx = __float2bfloat16(x - __bfloat162float(hx));
    __nv_bfloat16 ly = __float2bfloat16(y - __bfloat162float(hy));
    hi = pack_bf2(hx, hy);
    lo = pack_bf2(lx, ly);
}

// ---------------- CSR build ----------------
__global__ void zero_cnt_kernel() {
    int i = blockIdx.x * blockDim.x + threadIdx.x;
    if (i < N_NODES) g_cnt[i] = 0;
}
__global__ void count_kernel(const int* __restrict__ ei) {
    int e = blockIdx.x * blockDim.x + threadIdx.x;
    if (e < N_EDGES) atomicAdd(&g_cnt[ei[N_EDGES + e]], 1);
}
__global__ void scan1_kernel() {
    __shared__ int s[256];
    int t = threadIdx.x, i = blockIdx.x * 256 + t;
    int v = (i < N_NODES) ? g_cnt[i] : 0;
    s[t] = v; __syncthreads();
    #pragma unroll
    for (int d = 1; d < 256; d <<= 1) {
        int x = (t >= d) ? s[t - d] : 0;
        __syncthreads(); s[t] += x; __syncthreads();
    }
    if (i < N_NODES) g_off[i] = s[t] - v;
    if (t == 255) g_bsum[blockIdx.x] = s[255];
}
__global__ void scan23_kernel() {
    __shared__ int s[256];
    int t = threadIdx.x;
    s[t] = (t < SCAN_BLOCKS) ? g_bsum[t] : 0;
    __syncthreads();
    #pragma unroll
    for (int d = 1; d < 256; d <<= 1) {
        int x = (t >= d) ? s[t - d] : 0;
        __syncthreads(); s[t] += x; __syncthreads();
    }
    int blk = blockIdx.x;
    int add = (blk == 0) ? 0 : s[blk - 1];
    int i = blk * 256 + t;
    if (i < N_NODES) { int o = g_off[i] + add; g_off[i] = o; g_pos[i] = o; }
    if (i == N_NODES) g_off[N_NODES] = N_EDGES;
}
__global__ void fill_csr_kernel(const int* __restrict__ ei) {
    int e = blockIdx.x * blockDim.x + threadIdx.x;
    if (e < N_EDGES) {
        int t = ei[N_EDGES + e];
        g_csr[atomicAdd(&g_pos[t], 1)] = e;
    }
}

// ---------------- x -> split-bf16 A (K=128, row stride 64 words) ----------------
__global__ void convert_x_kernel(const float* __restrict__ x) {
    int idx = blockIdx.x * blockDim.x + threadIdx.x;
    if (idx >= N_NODES * 64) return;
    float2 v = ((const float2*)x)[idx];
    unsigned hi, lo;
    split2(v.x, v.y, hi, lo);
    g_Ahi[idx] = hi;
    g_Alo[idx] = lo;
}

// ---------------- W[K,64] -> split-bf16 B row-major ----------------
__global__ void prep_b_kernel(const float* __restrict__ W, int K) {
    int idx = blockIdx.x * blockDim.x + threadIdx.x;   // k*64 + n
    if (idx >= K * 64) return;
    float wv = W[idx];
    __nv_bfloat16 hi = __float2bfloat16(wv);
    g_Bhi[idx] = hi;
    g_Blo[idx] = __float2bfloat16(wv - __bfloat162float(hi));
}

// ---------------- edge aggregation -> split-bf16 A rows (K=192, stride 96 words) ----
__global__ void agg_kernel(const int* __restrict__ ei,
                           const float* __restrict__ ea, int hsel)
{
    __shared__ float4 sE[8][32];
    int w = threadIdx.x >> 5;
    int node = blockIdx.x * 8 + w;
    if (node >= N_NODES) return;
    int lane = threadIdx.x & 31;
    const float* H = sel_buf(hsel);
    int off = g_off[node];
    int deg = g_off[node + 1] - off;

    float s0x = 0.f, s0y = 0.f, s1x = 0.f, s1y = 0.f, s2x = 0.f, s2y = 0.f;

    for (int base = 0; base < deg; base += 32) {
        if (base + lane < deg) {
            int eid = __ldg(&g_csr[off + base + lane]);
            int src = __ldg(&ei[eid]);
            float a0 = __ldg(&ea[(size_t)eid * 3 + 0]);
            float a1 = __ldg(&ea[(size_t)eid * 3 + 1]);
            float a2 = __ldg(&ea[(size_t)eid * 3 + 2]);
            sE[w][lane] = make_float4(__int_as_float(src), a0, a1, a2);
        }
        __syncwarp();
        int m = min(32, deg - base);
        for (int k = 0; k < m; k++) {
            float4 ed = sE[w][k];
            int src = __float_as_int(ed.x);
            float2 hv = __ldg(&((const float2*)(H + (size_t)src * 64))[lane]);
            s0x += ed.y * hv.x; s0y += ed.y * hv.y;
            s1x += ed.z * hv.x; s1y += ed.z * hv.y;
            s2x += ed.w * hv.x; s2y += ed.w * hv.y;
        }
        __syncwarp();
    }

    float inv = 1.0f / fmaxf((float)deg, 1.0f);
    size_t rb = (size_t)node * 96;
    unsigned hi, lo;
    split2(s0x * inv, s0y * inv, hi, lo); g_Ahi[rb + lane]      = hi; g_Alo[rb + lane]      = lo;
    split2(s1x * inv, s1y * inv, hi, lo); g_Ahi[rb + 32 + lane] = hi; g_Alo[rb + 32 + lane] = lo;
    split2(s2x * inv, s2y * inv, hi, lo); g_Ahi[rb + 64 + lane] = hi; g_Alo[rb + 64 + lane] = lo;
}

// ---------------- WMMA bf16 split GEMM (smem-staged), fused epilogue ----------------
// D[row,n] = sum_k A[row,k]*W[k,n] (+bias; opt relu / row L2-norm).
// 256 threads = 8 warps; CTA tile 128 rows x 64 cols; warp tile 16x64 (4 frags).
// Per 16-k chunk: stage A(128x16) hi/lo + B(16x64) hi/lo in smem via coalesced
// word copies, then LDSM fragment loads. Split: D = Ahi*Bhi + Alo*Bhi + Ahi*Blo.
// Smem strides: A 24 elems (48B: LDSM rows hit distinct banks), B 72 elems (144B).
#define A_ST 24
#define B_ST 72
__global__ void __launch_bounds__(256)
gemm_wmma(int K, const float* __restrict__ bias,
          int do_relu, int do_norm, int csel, float* __restrict__ extout)
{
    __shared__ __align__(16) unsigned char smemraw[33 * 1024];
    __nv_bfloat16* sAh = (__nv_bfloat16*)smemraw;          // 128*24 = 3072 elems
    __nv_bfloat16* sAl = sAh + 128 * A_ST;                 // 3072
    __nv_bfloat16* sBh = sAl + 128 * A_ST;                 // 16*72 = 1152
    __nv_bfloat16* sBl = sBh + 16 * B_ST;                  // 1152  (total 16,896 B)
    float* sOut = (float*)smemraw;                         // epilogue reuse (32 KB)

    const int tid = threadIdx.x;
    const int wid = tid >> 5;
    const int lane = tid & 31;
    const int row0cta = blockIdx.x * 128;
    const int Kw = K >> 1;            // A row stride in bf16x2 words

    wmma::fragment<wmma::accumulator, 16, 16, 16, float> acc[4];
    #pragma unroll
    for (int j = 0; j < 4; j++) wmma::fill_fragment(acc[j], 0.0f);

    for (int k0 = 0; k0 < K; k0 += 16) {
        __syncthreads();
        // stage A chunk: 128 rows x 8 words (hi + lo)
        #pragma unroll
        for (int i = tid; i < 1024; i += 256) {
            int r = i >> 3, cw = i & 7;
            int grow = row0cta + r;
            unsigned vh = 0u, vl = 0u;
            if (grow < N_NODES) {
                size_t src = (size_t)grow * Kw + (k0 >> 1) + cw;
                vh = __ldg(&g_Ahi[src]);
                vl = __ldg(&g_Alo[src]);
            }
            ((unsigned*)sAh)[r * (A_ST / 2) + cw] = vh;
            ((unsigned*)sAl)[r * (A_ST / 2) + cw] = vl;
        }
        // stage B chunk: 16 rows x 32 words (hi + lo)
        #pragma unroll
        for (int i = tid; i < 512; i += 256) {
            int r = i >> 5, cw = i & 31;
            size_t src = (size_t)(k0 + r) * 32 + cw;
            ((unsigned*)sBh)[r * (B_ST / 2) + cw] = __ldg(&((const unsigned*)g_Bhi)[src]);
            ((unsigned*)sBl)[r * (B_ST / 2) + cw] = __ldg(&((const unsigned*)g_Blo)[src]);
        }
        __syncthreads();

        wmma::fragment<wmma::matrix_a, 16, 16, 16, __nv_bfloat16, wmma::row_major> ah, al;
        wmma::load_matrix_sync(ah, sAh + wid * 16 * A_ST, A_ST);
        wmma::load_matrix_sync(al, sAl + wid * 16 * A_ST, A_ST);
        #pragma unroll
        for (int j = 0; j < 4; j++) {
            wmma::fragment<wmma::matrix_b, 16, 16, 16, __nv_bfloat16, wmma::row_major> bh, bl;
            wmma::load_matrix_sync(bh, sBh + j * 16, B_ST);
            wmma::load_matrix_sync(bl, sBl + j * 16, B_ST);
            wmma::mma_sync(acc[j], ah, bh, acc[j]);
            wmma::mma_sync(acc[j], al, bh, acc[j]);
            wmma::mma_sync(acc[j], ah, bl, acc[j]);
        }
    }

    __syncthreads();   // staging buffers dead; reuse as epilogue tile
    #pragma unroll
    for (int j = 0; j < 4; j++)
        wmma::store_matrix_sync(&sOut[wid * 1024 + j * 16], acc[j], 64, wmma::mem_row_major);
    __syncwarp();

    // epilogue: 2 lanes per row (lane = r + 16*half); each half covers 32 cols
    int r = lane & 15, half = lane >> 4;
    int row = row0cta + wid * 16 + r;
    const float* src = &sOut[wid * 1024 + r * 64 + half * 32];
    float v[32];
    float ss = 0.0f;
    #pragma unroll
    for (int j = 0; j < 32; j++) {
        v[j] = src[j] + __ldg(&bias[half * 32 + j]);
        if (do_relu) v[j] = fmaxf(v[j], 0.0f);
        ss += v[j] * v[j];
    }
    if (do_norm) {
        ss += __shfl_xor_sync(0xffffffffu, ss, 16);  // combine halves of same row
        float rr = 1.0f / fmaxf(sqrtf(ss), 1e-12f);
        #pragma unroll
        for (int j = 0; j < 32; j++) v[j] *= rr;
    }
    if (row < N_NODES) {
        float* C = (csel < 0) ? extout : sel_buf(csel);
        float4* po = (float4*)(C + (size_t)row * 64 + half * 32);
        #pragma unroll
        for (int j = 0; j < 8; j++)
            po[j] = make_float4(v[4 * j], v[4 * j + 1], v[4 * j + 2], v[4 * j + 3]);
    }
}

// ---------------- launch (kernel launches ONLY — graph-capture safe) ----------------
extern "C" void kernel_launch(void* const* d_in, const int* in_sizes, int n_in,
                              void* d_out, int out_size)
{
    const float* x     = (const float*)d_in[0];
    const int*   ei    = (const int*)  d_in[1];   // [2, E]
    const float* ea    = (const float*)d_in[2];   // [E, 3]
    const float* pre_w = (const float*)d_in[3];   // [128, 64]
    const float* pre_b = (const float*)d_in[4];   // [64]
    const float* w[3]  = {(const float*)d_in[5], (const float*)d_in[7], (const float*)d_in[9]};
    const float* b[3]  = {(const float*)d_in[6], (const float*)d_in[8], (const float*)d_in[10]};
    float* out = (float*)d_out;

    const int gemm_blocks = (N_NODES + 127) / 128;   // 391

    // ---- CSR build ----
    zero_cnt_kernel<<<(N_NODES + 255) / 256, 256>>>();
    count_kernel<<<(N_EDGES + 255) / 256, 256>>>(ei);
    scan1_kernel<<<SCAN_BLOCKS, 256>>>();
    scan23_kernel<<<SCAN_BLOCKS + 1, 256>>>();
    fill_csr_kernel<<<(N_EDGES + 255) / 256, 256>>>(ei);

    // ---- linear_pre: H0 = x @ pre_w + pre_b (WMMA, K=128) ----
    convert_x_kernel<<<(N_NODES * 64 + 255) / 256, 256>>>(x);
    prep_b_kernel<<<(IN_DIM * 64 + 255) / 256, 256>>>(pre_w, IN_DIM);
    gemm_wmma<<<gemm_blocks, 256>>>(IN_DIM, pre_b, 0, 0, 0, nullptr);

    int hin = 0, hout = 1;
    for (int l = 0; l < 3; l++) {
        agg_kernel<<<(N_NODES + 7) / 8, 256>>>(ei, ea, hin);       // -> split-bf16 A (K=192)
        prep_b_kernel<<<(192 * 64 + 255) / 256, 256>>>(w[l], 192);
        if (l < 2) {
            gemm_wmma<<<gemm_blocks, 256>>>(192, b[l], 1, 0, hout, nullptr);
        } else {
            gemm_wmma<<<gemm_blocks, 256>>>(192, b[l], 0, 1, -1, out);
        }
        int t = hin; hin = hout; hout = t;
    }
}

// round 12
// speedup vs baseline: 1.4388x; 1.0734x over previous
#include <cuda_runtime.h>
#include <cuda_bf16.h>
#include <mma.h>
#include <math.h>
#include <stdint.h>

using namespace nvcuda;

#define N_NODES 50000
#define N_EDGES 800000
#define IN_DIM  128
#define FEAT    64
#define SCAN_BLOCKS 196   // ceil(50001/256)
// B-image element offsets: pre_w, w1, w2, w3
#define NXW 3200000       // N_NODES*64 float2-units of x

// ---------------- scratch (static device globals; no allocation) ----------------
__device__ float    g_H0[N_NODES * FEAT];
__device__ float    g_H1[N_NODES * FEAT];
__device__ unsigned g_Ahi[N_NODES * 96];     // split-bf16 A, packed bf16x2, row stride K/2 words
__device__ unsigned g_Alo[N_NODES * 96];
__device__ __nv_bfloat16 g_Bhi[45056];       // pre_w(8192) + 3x w(12288), row-major [K,64]
__device__ __nv_bfloat16 g_Blo[45056];
__device__ int      g_cnt[N_NODES];
__device__ int      g_off[N_NODES + 1];
__device__ int      g_pos[N_NODES];
__device__ int      g_csr[N_EDGES];
__device__ int      g_bsum[256];

__device__ __forceinline__ float* sel_buf(int s) { return (s == 0) ? g_H0 : g_H1; }

__device__ __forceinline__ unsigned pack_bf2(__nv_bfloat16 a, __nv_bfloat16 b) {
    return ((unsigned)__bfloat16_as_ushort(b) << 16) | (unsigned)__bfloat16_as_ushort(a);
}
__device__ __forceinline__ void split2(float x, float y, unsigned& hi, unsigned& lo) {
    __nv_bfloat16 hx = __float2bfloat16(x), hy = __float2bfloat16(y);
    __nv_bfloat16 lx = __float2bfloat16(x - __bfloat162float(hx));
    __nv_bfloat16 ly = __float2bfloat16(y - __bfloat162float(hy));
    hi = pack_bf2(hx, hy);
    lo = pack_bf2(lx, ly);
}

// ---------------- CSR build ----------------
__global__ void zero_cnt_kernel() {
    int i = blockIdx.x * blockDim.x + threadIdx.x;
    if (i < N_NODES) g_cnt[i] = 0;
}
__global__ void count_kernel(const int* __restrict__ ei) {
    int e = blockIdx.x * blockDim.x + threadIdx.x;
    if (e < N_EDGES) atomicAdd(&g_cnt[ei[N_EDGES + e]], 1);
}
__global__ void scan1_kernel() {
    __shared__ int s[256];
    int t = threadIdx.x, i = blockIdx.x * 256 + t;
    int v = (i < N_NODES) ? g_cnt[i] : 0;
    s[t] = v; __syncthreads();
    #pragma unroll
    for (int d = 1; d < 256; d <<= 1) {
        int x = (t >= d) ? s[t - d] : 0;
        __syncthreads(); s[t] += x; __syncthreads();
    }
    if (i < N_NODES) g_off[i] = s[t] - v;
    if (t == 255) g_bsum[blockIdx.x] = s[255];
}
__global__ void scan23_kernel() {
    __shared__ int s[256];
    int t = threadIdx.x;
    s[t] = (t < SCAN_BLOCKS) ? g_bsum[t] : 0;
    __syncthreads();
    #pragma unroll
    for (int d = 1; d < 256; d <<= 1) {
        int x = (t >= d) ? s[t - d] : 0;
        __syncthreads(); s[t] += x; __syncthreads();
    }
    int blk = blockIdx.x;
    int add = (blk == 0) ? 0 : s[blk - 1];
    int i = blk * 256 + t;
    if (i < N_NODES) { int o = g_off[i] + add; g_off[i] = o; g_pos[i] = o; }
    if (i == N_NODES) g_off[N_NODES] = N_EDGES;
}
__global__ void fill_csr_kernel(const int* __restrict__ ei) {
    int e = blockIdx.x * blockDim.x + threadIdx.x;
    if (e < N_EDGES) {
        int t = ei[N_EDGES + e];
        g_csr[atomicAdd(&g_pos[t], 1)] = e;
    }
}

// ---------------- fused prep: x -> split-bf16 A (K=128) + all weights -> B image ----
__global__ void prep_all_kernel(const float* __restrict__ x,
                                const float* __restrict__ pre_w,
                                const float* __restrict__ w1,
                                const float* __restrict__ w2,
                                const float* __restrict__ w3)
{
    int idx = blockIdx.x * blockDim.x + threadIdx.x;
    if (idx < NXW) {
        float2 v = ((const float2*)x)[idx];
        unsigned hi, lo;
        split2(v.x, v.y, hi, lo);
        g_Ahi[idx] = hi;
        g_Alo[idx] = lo;
    } else {
        int j = idx - NXW;
        if (j < 45056) {
            const float* W; int off;
            if (j < 8192)       { W = pre_w; off = 0;     }
            else if (j < 20480) { W = w1;    off = 8192;  j -= 8192;  }
            else if (j < 32768) { W = w2;    off = 20480; j -= 20480; }
            else                { W = w3;    off = 32768; j -= 32768; }
            float wv = W[j];
            __nv_bfloat16 hi = __float2bfloat16(wv);
            g_Bhi[off + j] = hi;
            g_Blo[off + j] = __float2bfloat16(wv - __bfloat162float(hi));
        }
    }
}

// ---------------- edge aggregation -> split-bf16 A rows (K=192, stride 96 words) ----
__global__ void agg_kernel(const int* __restrict__ ei,
                           const float* __restrict__ ea, int hsel)
{
    __shared__ float4 sE[8][32];
    int w = threadIdx.x >> 5;
    int node = blockIdx.x * 8 + w;
    if (node >= N_NODES) return;
    int lane = threadIdx.x & 31;
    const float* H = sel_buf(hsel);
    int off = g_off[node];
    int deg = g_off[node + 1] - off;

    float s0x = 0.f, s0y = 0.f, s1x = 0.f, s1y = 0.f, s2x = 0.f, s2y = 0.f;

    for (int base = 0; base < deg; base += 32) {
        if (base + lane < deg) {
            int eid = __ldg(&g_csr[off + base + lane]);
            int src = __ldg(&ei[eid]);
            float a0 = __ldg(&ea[(size_t)eid * 3 + 0]);
            float a1 = __ldg(&ea[(size_t)eid * 3 + 1]);
            float a2 = __ldg(&ea[(size_t)eid * 3 + 2]);
            sE[w][lane] = make_float4(__int_as_float(src), a0, a1, a2);
        }
        __syncwarp();
        int m = min(32, deg - base);
        for (int k = 0; k < m; k++) {
            float4 ed = sE[w][k];
            int src = __float_as_int(ed.x);
            float2 hv = __ldg(&((const float2*)(H + (size_t)src * 64))[lane]);
            s0x += ed.y * hv.x; s0y += ed.y * hv.y;
            s1x += ed.z * hv.x; s1y += ed.z * hv.y;
            s2x += ed.w * hv.x; s2y += ed.w * hv.y;
        }
        __syncwarp();
    }

    float inv = 1.0f / fmaxf((float)deg, 1.0f);
    size_t rb = (size_t)node * 96;
    unsigned hi, lo;
    split2(s0x * inv, s0y * inv, hi, lo); g_Ahi[rb + lane]      = hi; g_Alo[rb + lane]      = lo;
    split2(s1x * inv, s1y * inv, hi, lo); g_Ahi[rb + 32 + lane] = hi; g_Alo[rb + 32 + lane] = lo;
    split2(s2x * inv, s2y * inv, hi, lo); g_Ahi[rb + 64 + lane] = hi; g_Alo[rb + 64 + lane] = lo;
}

// ---------------- WMMA bf16 split GEMM (pipelined), fused epilogue ----------------
// D[row,n] = sum_k A[row,k]*W[k,n] (+bias; opt relu / row L2-norm).
// 256 threads = 8 warps; CTA tile 128 x 64; warp tile 16x64 (4 frags).
// k-chunk 32, register-prefetch of chunk c+1 overlapped with compute of chunk c.
// Smem strides: A 40 elems (80B: LDSM rows conflict-free), B 72 elems (144B).
#define GA_ST 40
#define GB_ST 72
__global__ void __launch_bounds__(256)
gemm_wmma(int K, int boff, const float* __restrict__ bias,
          int do_relu, int do_norm, int csel, float* __restrict__ extout)
{
    __shared__ __align__(16) unsigned char smemraw[33 * 1024];
    __nv_bfloat16* sAh = (__nv_bfloat16*)smemraw;   // 128*40 = 5120 elems (10240 B)
    __nv_bfloat16* sAl = sAh + 128 * GA_ST;         // 10240 B
    __nv_bfloat16* sBh = sAl + 128 * GA_ST;         // 32*72 = 2304 elems (4608 B)
    __nv_bfloat16* sBl = sBh + 32 * GB_ST;          // 4608 B   (total 29,696 B)
    float* sOut = (float*)smemraw;                  // epilogue reuse (32 KB)

    const int tid = threadIdx.x;
    const int wid = tid >> 5;
    const int lane = tid & 31;
    const int row0cta = blockIdx.x * 128;
    const int chunks = K >> 5;

    const __nv_bfloat16* Ah = (const __nv_bfloat16*)g_Ahi;
    const __nv_bfloat16* Al = (const __nv_bfloat16*)g_Alo;
    const __nv_bfloat16* Bh = g_Bhi + boff;
    const __nv_bfloat16* Bl = g_Blo + boff;

    // copy-thread mapping (constant across chunks)
    const int ar0 = tid >> 2, aq = tid & 3;         // A: rows 0..63 (first half)
    const int ar1 = 64 + ar0;                       //    rows 64..127 (second half)
    const int brow = tid >> 3, bq = tid & 7;        // B: 32 rows x 8 uint4
    const int ga0 = row0cta + ar0, ga1 = row0cta + ar1;

    wmma::fragment<wmma::accumulator, 16, 16, 16, float> acc[4];
    #pragma unroll
    for (int j = 0; j < 4; j++) wmma::fill_fragment(acc[j], 0.0f);

    uint4 rah0, rah1, ral0, ral1, rbh, rbl;
    const uint4 z4 = make_uint4(0, 0, 0, 0);

    // prefetch chunk 0
    {
        int k0 = 0;
        rah0 = (ga0 < N_NODES) ? ((const uint4*)(Ah + (size_t)ga0 * K + k0))[aq] : z4;
        rah1 = (ga1 < N_NODES) ? ((const uint4*)(Ah + (size_t)ga1 * K + k0))[aq] : z4;
        ral0 = (ga0 < N_NODES) ? ((const uint4*)(Al + (size_t)ga0 * K + k0))[aq] : z4;
        ral1 = (ga1 < N_NODES) ? ((const uint4*)(Al + (size_t)ga1 * K + k0))[aq] : z4;
        rbh  = ((const uint4*)(Bh + (size_t)(k0 + brow) * 64))[bq];
        rbl  = ((const uint4*)(Bl + (size_t)(k0 + brow) * 64))[bq];
    }

    for (int c = 0; c < chunks; c++) {
        __syncthreads();   // smem consumers of chunk c-1 done
        // regs -> smem (uint4; A row = 5 uint4 at stride 40 elems, B row = 9)
        ((uint4*)sAh)[ar0 * 5 + aq] = rah0;
        ((uint4*)sAh)[ar1 * 5 + aq] = rah1;
        ((uint4*)sAl)[ar0 * 5 + aq] = ral0;
        ((uint4*)sAl)[ar1 * 5 + aq] = ral1;
        ((uint4*)sBh)[brow * 9 + bq] = rbh;
        ((uint4*)sBl)[brow * 9 + bq] = rbl;
        // prefetch chunk c+1 (overlaps with compute below)
        if (c + 1 < chunks) {
            int k0 = (c + 1) << 5;
            rah0 = (ga0 < N_NODES) ? ((const uint4*)(Ah + (size_t)ga0 * K + k0))[aq] : z4;
            rah1 = (ga1 < N_NODES) ? ((const uint4*)(Ah + (size_t)ga1 * K + k0))[aq] : z4;
            ral0 = (ga0 < N_NODES) ? ((const uint4*)(Al + (size_t)ga0 * K + k0))[aq] : z4;
            ral1 = (ga1 < N_NODES) ? ((const uint4*)(Al + (size_t)ga1 * K + k0))[aq] : z4;
            rbh  = ((const uint4*)(Bh + (size_t)(k0 + brow) * 64))[bq];
            rbl  = ((const uint4*)(Bl + (size_t)(k0 + brow) * 64))[bq];
        }
        __syncthreads();   // staging visible
        #pragma unroll
        for (int ks = 0; ks < 2; ks++) {
            wmma::fragment<wmma::matrix_a, 16, 16, 16, __nv_bfloat16, wmma::row_major> ah, al;
            wmma::load_matrix_sync(ah, sAh + wid * 16 * GA_ST + ks * 16, GA_ST);
            wmma::load_matrix_sync(al, sAl + wid * 16 * GA_ST + ks * 16, GA_ST);
            #pragma unroll
            for (int j = 0; j < 4; j++) {
                wmma::fragment<wmma::matrix_b, 16, 16, 16, __nv_bfloat16, wmma::row_major> bh, bl;
                wmma::load_matrix_sync(bh, sBh + ks * 16 * GB_ST + j * 16, GB_ST);
                wmma::load_matrix_sync(bl, sBl + ks * 16 * GB_ST + j * 16, GB_ST);
                wmma::mma_sync(acc[j], ah, bh, acc[j]);
                wmma::mma_sync(acc[j], al, bh, acc[j]);
                wmma::mma_sync(acc[j], ah, bl, acc[j]);
            }
        }
    }

    __syncthreads();   // staging dead; reuse as epilogue tile
    #pragma unroll
    for (int j = 0; j < 4; j++)
        wmma::store_matrix_sync(&sOut[wid * 1024 + j * 16], acc[j], 64, wmma::mem_row_major);
    __syncwarp();

    // epilogue: 2 lanes per row (lane = r + 16*half); each half covers 32 cols
    int r = lane & 15, half = lane >> 4;
    int row = row0cta + wid * 16 + r;
    const float* src = &sOut[wid * 1024 + r * 64 + half * 32];
    float v[32];
    float ss = 0.0f;
    #pragma unroll
    for (int j = 0; j < 32; j++) {
        v[j] = src[j] + __ldg(&bias[half * 32 + j]);
        if (do_relu) v[j] = fmaxf(v[j], 0.0f);
        ss += v[j] * v[j];
    }
    if (do_norm) {
        ss += __shfl_xor_sync(0xffffffffu, ss, 16);  // combine halves of same row
        float rr = 1.0f / fmaxf(sqrtf(ss), 1e-12f);
        #pragma unroll
        for (int j = 0; j < 32; j++) v[j] *= rr;
    }
    if (row < N_NODES) {
        float* C = (csel < 0) ? extout : sel_buf(csel);
        float4* po = (float4*)(C + (size_t)row * 64 + half * 32);
        #pragma unroll
        for (int j = 0; j < 8; j++)
            po[j] = make_float4(v[4 * j], v[4 * j + 1], v[4 * j + 2], v[4 * j + 3]);
    }
}

// ---------------- launch (kernel launches ONLY — graph-capture safe) ----------------
extern "C" void kernel_launch(void* const* d_in, const int* in_sizes, int n_in,
                              void* d_out, int out_size)
{
    const float* x     = (const float*)d_in[0];
    const int*   ei    = (const int*)  d_in[1];   // [2, E]
    const float* ea    = (const float*)d_in[2];   // [E, 3]
    const float* pre_w = (const float*)d_in[3];   // [128, 64]
    const float* pre_b = (const float*)d_in[4];   // [64]
    const float* w[3]  = {(const float*)d_in[5], (const float*)d_in[7], (const float*)d_in[9]};
    const float* b[3]  = {(const float*)d_in[6], (const float*)d_in[8], (const float*)d_in[10]};
    float* out = (float*)d_out;

    const int gemm_blocks = (N_NODES + 127) / 128;   // 391

    // ---- CSR build ----
    zero_cnt_kernel<<<(N_NODES + 255) / 256, 256>>>();
    count_kernel<<<(N_EDGES + 255) / 256, 256>>>(ei);
    scan1_kernel<<<SCAN_BLOCKS, 256>>>();
    scan23_kernel<<<SCAN_BLOCKS + 1, 256>>>();
    fill_csr_kernel<<<(N_EDGES + 255) / 256, 256>>>(ei);

    // ---- fused prep: x conversion + all weight conversions ----
    prep_all_kernel<<<(NXW + 45056 + 255) / 256, 256>>>(x, pre_w, w[0], w[1], w[2]);

    // ---- linear_pre: H0 = x @ pre_w + pre_b (K=128, B offset 0) ----
    gemm_wmma<<<gemm_blocks, 256>>>(IN_DIM, 0, pre_b, 0, 0, 0, nullptr);

    int hin = 0, hout = 1;
    for (int l = 0; l < 3; l++) {
        agg_kernel<<<(N_NODES + 7) / 8, 256>>>(ei, ea, hin);     // -> split-bf16 A (K=192)
        int boff = 8192 + l * 12288;
        if (l < 2) {
            gemm_wmma<<<gemm_blocks, 256>>>(192, boff, b[l], 1, 0, hout, nullptr);
        } else {
            gemm_wmma<<<gemm_blocks, 256>>>(192, boff, b[l], 0, 1, -1, out);
        }
        int t = hin; hin = hout; hout = t;
    }
}